// round 8
// baseline (speedup 1.0000x reference)
#include <cuda_runtime.h>
#include <cstdint>
#include <cstddef>

#define Mdim 256
#define Ndim 1024
#define Bdim 16384
#define Kiter 16
#define Pk 50u
#define SP_CAP 1024

// ---------------------------------------------------------------------------
// Scratch (allocation-free __device__ globals). Batch-major layout.
// ---------------------------------------------------------------------------
__device__ float  g_x [(size_t)Bdim * Ndim];     // x (B,N) fp32
__device__ float  g_r [(size_t)Bdim * Mdim];     // r (B,M) fp32
__device__ float  g_c [(size_t)Bdim * Ndim];     // c (B,N) fp32
__device__ float  g_wt[(size_t)Ndim * Mdim];     // W^T (N,M), k=m contiguous
__device__ float  g_phiT[(size_t)Ndim * Mdim];   // phi^T (N,M)
__device__ int    g_nnz[Bdim];                   // per-row nonzero count
__device__ float2 g_sp[(size_t)Bdim * SP_CAP];   // (smem_off_as_float, val)

// ---------------------------------------------------------------------------
// PTX helpers (plain-sm_103-legal)
// ---------------------------------------------------------------------------
__device__ __forceinline__ void cp_async16(uint32_t saddr, const void* gaddr) {
    asm volatile("cp.async.cg.shared.global [%0], [%1], 16;\n"
                 :: "r"(saddr), "l"(gaddr));
}
#define CP_COMMIT() asm volatile("cp.async.commit_group;\n" ::: "memory")
#define CP_WAIT0()  asm volatile("cp.async.wait_group 0;\n" ::: "memory")
#define CP_WAIT1()  asm volatile("cp.async.wait_group 1;\n" ::: "memory")

__device__ __forceinline__ void split_tf32(float v, uint32_t& hi, uint32_t& lo) {
    uint32_t h;
    asm("cvt.rna.tf32.f32 %0, %1;" : "=r"(h) : "f"(v));
    float hf = __uint_as_float(h);
    asm("cvt.rna.tf32.f32 %0, %1;" : "=r"(lo) : "f"(v - hf));
    hi = h;
}

__device__ __forceinline__ void mma_tf32(float* d, const uint32_t* a,
                                         const uint32_t* b) {
    asm volatile(
        "mma.sync.aligned.m16n8k8.row.col.f32.tf32.tf32.f32 "
        "{%0,%1,%2,%3}, {%4,%5,%6,%7}, {%8,%9}, {%0,%1,%2,%3};"
        : "+f"(d[0]), "+f"(d[1]), "+f"(d[2]), "+f"(d[3])
        : "r"(a[0]), "r"(a[1]), "r"(a[2]), "r"(a[3]),
          "r"(b[0]), "r"(b[1]));
}

// ---------------------------------------------------------------------------
// Dense TF32x3 GEMM (R4-proven): D(B x Nrows) = A(B,Kd) @ Bm(Nrows,Kd)^T
// fp32 operands, in-register tf32 hi/lo split at fragment load.
// Tile 128x128x16, 256 threads (2x4 warps), warp tile 64x32.
// ---------------------------------------------------------------------------
#define KTILE 16
#define ROWPAD 20
#define OP_FLOATS (128 * ROWPAD)
#define STAGE_BYTES (2 * OP_FLOATS * 4)
#define GEMM_SMEM (2 * STAGE_BYTES)

__global__ void __launch_bounds__(256)
gemm_tc(const float* __restrict__ A, const float* __restrict__ Bm,
        float* __restrict__ D, int Kd, int CStride)
{
    extern __shared__ float sm[];
    const int tid  = threadIdx.x;
    const int wid  = tid >> 5;
    const int lane = tid & 31;
    const int gid  = lane >> 2;
    const int tig  = lane & 3;
    const int wm   = wid >> 2;
    const int wn   = wid & 3;
    const int b0   = blockIdx.y * 128;
    const int n0   = blockIdx.x * 128;
    const uint32_t smbase = (uint32_t)__cvta_generic_to_shared(sm);

    float acc[4][4][4];
#pragma unroll
    for (int i = 0; i < 4; i++)
#pragma unroll
        for (int j = 0; j < 4; j++)
#pragma unroll
            for (int q = 0; q < 4; q++) acc[i][j][q] = 0.0f;

    auto load_stage = [&](int t, int buf) {
        const int k0 = t * KTILE;
        const uint32_t sb = smbase + buf * STAGE_BYTES;
#pragma unroll
        for (int l = 0; l < 2; l++) {
            int c   = tid + l * 256;
            int row = c >> 2;
            int ch  = c & 3;
            cp_async16(sb + row * (ROWPAD * 4) + ch * 16,
                       A + (size_t)(b0 + row) * Kd + k0 + ch * 4);
            cp_async16(sb + OP_FLOATS * 4 + row * (ROWPAD * 4) + ch * 16,
                       Bm + (size_t)(n0 + row) * Kd + k0 + ch * 4);
        }
    };

    const int T = Kd / KTILE;
    load_stage(0, 0);
    CP_COMMIT();

    for (int t = 0; t < T; t++) {
        const int buf = t & 1;
        if (t + 1 < T) {
            load_stage(t + 1, buf ^ 1);
            CP_COMMIT();
            CP_WAIT1();
        } else {
            CP_WAIT0();
        }
        __syncthreads();

        const float* As = sm + buf * (STAGE_BYTES / 4);
        const float* Bs = As + OP_FLOATS;

#pragma unroll
        for (int s = 0; s < 2; s++) {
            const int kb = s * 8;
            uint32_t bhi[4][2], blo[4][2];
#pragma unroll
            for (int nt = 0; nt < 4; nt++) {
                int n = wn * 32 + nt * 8 + gid;
                split_tf32(Bs[n * ROWPAD + kb + tig], bhi[nt][0], blo[nt][0]);
                split_tf32(Bs[n * ROWPAD + kb + tig + 4], bhi[nt][1], blo[nt][1]);
            }
#pragma unroll
            for (int mt = 0; mt < 4; mt++) {
                int m = wm * 64 + mt * 16 + gid;
                uint32_t ahi[4], alo[4];
                split_tf32(As[m * ROWPAD + kb + tig], ahi[0], alo[0]);
                split_tf32(As[(m + 8) * ROWPAD + kb + tig], ahi[1], alo[1]);
                split_tf32(As[m * ROWPAD + kb + tig + 4], ahi[2], alo[2]);
                split_tf32(As[(m + 8) * ROWPAD + kb + tig + 4], ahi[3], alo[3]);
#pragma unroll
                for (int nt = 0; nt < 4; nt++) {
                    mma_tf32(acc[mt][nt], ahi, bhi[nt]);
                    mma_tf32(acc[mt][nt], ahi, blo[nt]);
                    mma_tf32(acc[mt][nt], alo, bhi[nt]);
                }
            }
        }
        __syncthreads();
    }

#pragma unroll
    for (int mt = 0; mt < 4; mt++) {
        int r0 = b0 + wm * 64 + mt * 16 + gid;
#pragma unroll
        for (int nt = 0; nt < 4; nt++) {
            int col = n0 + wn * 32 + nt * 8 + tig * 2;
            *(float2*)(D + (size_t)r0 * CStride + col) =
                make_float2(acc[mt][nt][0], acc[mt][nt][1]);
            *(float2*)(D + (size_t)(r0 + 8) * CStride + col) =
                make_float2(acc[mt][nt][2], acc[mt][nt][3]);
        }
    }
}

// ---------------------------------------------------------------------------
// Sparse GEMM1: r(B,M) = sparse(x)(B,N) @ phiT(N,M) - y(B,M)   [fp32 exact]
// CTA owns m-strip [m0, m0+32) with full phiT[:, strip] in 128KB smem.
// Warp walks 16 batch rows' compacted lists; lane owns one m column.
// ---------------------------------------------------------------------------
#define SPG_SMEM (Ndim * 32 * 4)     // 131072 B

__global__ void __launch_bounds__(256)
sparse_gemm_kernel(const float* __restrict__ phiT,
                   const float2* __restrict__ sp,
                   const int* __restrict__ nnzArr,
                   const float* __restrict__ y,
                   float* __restrict__ r)
{
    extern __shared__ float s[];
    const int tid  = threadIdx.x;
    const int w    = tid >> 5;
    const int lane = tid & 31;
    const int m0   = blockIdx.x * 32;
    const int b0   = blockIdx.y * 128;
    const uint32_t sb = (uint32_t)__cvta_generic_to_shared(s);

    // load phiT[:, m0:m0+32] -> s[n*32 + mm]; 8192 16B-chunks, 32/thread
#pragma unroll
    for (int l = 0; l < 32; l++) {
        int idx = tid + l * 256;
        int n   = idx >> 3;
        int ch  = idx & 7;
        cp_async16(sb + (n * 32 + ch * 4) * 4,
                   phiT + (size_t)n * Mdim + m0 + ch * 4);
    }
    CP_COMMIT();
    CP_WAIT0();
    __syncthreads();

    for (int i = 0; i < 16; i++) {
        int b = b0 + w * 16 + i;
        const float2* lst = sp + (size_t)b * SP_CAP;
        int nnz = nnzArr[b];
        float a0 = 0.f, a1 = 0.f, a2 = 0.f, a3 = 0.f;
        int j = 0;
        for (; j + 4 <= nnz; j += 4) {
            float4 e0 = *(const float4*)(lst + j);
            float4 e1 = *(const float4*)(lst + j + 2);
            a0 = fmaf(e0.y, s[__float_as_int(e0.x) + lane], a0);
            a1 = fmaf(e0.w, s[__float_as_int(e0.z) + lane], a1);
            a2 = fmaf(e1.y, s[__float_as_int(e1.x) + lane], a2);
            a3 = fmaf(e1.w, s[__float_as_int(e1.z) + lane], a3);
        }
        for (; j < nnz; j++) {
            float2 e = lst[j];
            a0 = fmaf(e.y, s[__float_as_int(e.x) + lane], a0);
        }
        size_t o = (size_t)b * Mdim + m0 + lane;
        r[o] = ((a0 + a1) + (a2 + a3)) - y[o];
    }
}

// ---------------------------------------------------------------------------
// Fused update on (B,N): one warp per batch row.
// v = x - gamma*c; thr = exact Pk-th largest |v|; res = keep ? v : soft(v).
// LAST=0: write res to x and emit compacted (smem_off, val) list.
// LAST=1: write res to out only.
// ---------------------------------------------------------------------------
template<int LAST>
__global__ void __launch_bounds__(256)
update_kernel(const float* __restrict__ x, float* __restrict__ xout,
              const float* __restrict__ c,
              float2* __restrict__ sp, int* __restrict__ nnzArr,
              const float* __restrict__ gammaArr,
              const float* __restrict__ thetaArr, int it)
{
    __shared__ float    v[8][1024];
    __shared__ unsigned hist[8][256];

    const int tid  = threadIdx.x;
    const int w    = tid >> 5;
    const int lane = tid & 31;
    const int brow = blockIdx.x * 8 + w;
    const size_t gbase = (size_t)brow * Ndim;
    const float gamma = gammaArr[it];
    const float theta = thetaArr[it];

    float xabs[32];
#pragma unroll
    for (int i = 0; i < 8; i++) {
        int n = i * 128 + lane * 4;
        float4 xv = *(const float4*)(x + gbase + n);
        float4 cc = *(const float4*)(c + gbase + n);
        xabs[i * 4 + 0] = fabsf(xv.x);
        xabs[i * 4 + 1] = fabsf(xv.y);
        xabs[i * 4 + 2] = fabsf(xv.z);
        xabs[i * 4 + 3] = fabsf(xv.w);
        float4 vv;
        vv.x = xv.x - gamma * cc.x;
        vv.y = xv.y - gamma * cc.y;
        vv.z = xv.z - gamma * cc.z;
        vv.w = xv.w - gamma * cc.w;
        *(float4*)(&v[w][n]) = vv;
    }
    __syncwarp();

    // exact radix select of Pk-th largest |v| over 1024 values
    unsigned prefix = 0u, mask = 0u, k = Pk;
    unsigned* h = hist[w];
#pragma unroll
    for (int pass = 0; pass < 4; pass++) {
        const int shift = 24 - 8 * pass;
#pragma unroll
        for (int i = lane; i < 256; i += 32) h[i] = 0u;
        __syncwarp();
        for (int n = lane; n < 1024; n += 32) {
            unsigned e = __float_as_uint(v[w][n]) & 0x7FFFFFFFu;
            if ((e & mask) == prefix)
                atomicAdd(&h[(e >> shift) & 0xFFu], 1u);
        }
        __syncwarp();
        unsigned loc[8];
        unsigned sfx = 0u;
#pragma unroll
        for (int rr = 7; rr >= 0; rr--) { sfx += h[lane * 8 + rr]; loc[rr] = sfx; }
        unsigned inc = sfx;
#pragma unroll
        for (int off = 1; off < 32; off <<= 1) {
            unsigned t = __shfl_down_sync(0xffffffffu, inc, off);
            if (lane + off < 32) inc += t;
        }
        const unsigned above = inc - sfx;
        unsigned dfound = 0u, kfound = 0u;
        bool found = false;
#pragma unroll
        for (int rr = 7; rr >= 0; rr--) {
            unsigned cge  = above + loc[rr];
            unsigned cge1 = above + (rr < 7 ? loc[rr + 1] : 0u);
            if (cge >= k && cge1 < k) {
                dfound = (unsigned)(lane * 8 + rr);
                kfound = k - cge1;
                found = true;
            }
        }
        unsigned bal = __ballot_sync(0xffffffffu, found);
        int src = __ffs(bal) - 1;
        dfound = __shfl_sync(0xffffffffu, dfound, src);
        kfound = __shfl_sync(0xffffffffu, kfound, src);
        k = kfound;
        prefix |= dfound << shift;
        mask   |= 0xFFu << shift;
        __syncwarp();
    }
    const float thrv = __uint_as_float(prefix);

    // Phase 3: apply threshold; write x/out; emit compacted list (LAST=0)
    int lbase = 0;
    float2* dst = LAST ? nullptr : (sp + (size_t)brow * SP_CAP);
#pragma unroll
    for (int i = 0; i < 8; i++) {
        int n = i * 128 + lane * 4;
        float4 vv = *(const float4*)(&v[w][n]);
        float res[4];
        const float* vp = &vv.x;
#pragma unroll
        for (int jc = 0; jc < 4; jc++) {
            float val = vp[jc];
            float av = fabsf(val);
            float th = theta * (1.0f / (xabs[i * 4 + jc] / 0.1f + 1.0f));
            float st = copysignf(fmaxf(av - th, 0.0f), val);
            res[jc] = (av > thrv) ? val : st;
        }
        *(float4*)(xout + gbase + n) = make_float4(res[0], res[1], res[2], res[3]);

        if (!LAST) {
            unsigned cnt = (res[0] != 0.0f) + (res[1] != 0.0f) +
                           (res[2] != 0.0f) + (res[3] != 0.0f);
            unsigned inc = cnt;
#pragma unroll
            for (int off = 1; off < 32; off <<= 1) {
                unsigned t = __shfl_up_sync(0xffffffffu, inc, off);
                if (lane >= off) inc += t;
            }
            int off = lbase + (int)(inc - cnt);
#pragma unroll
            for (int jc = 0; jc < 4; jc++) {
                if (res[jc] != 0.0f) {
                    dst[off] = make_float2(__int_as_float((n + jc) * 32), res[jc]);
                    off++;
                }
            }
            lbase += (int)__shfl_sync(0xffffffffu, inc, 31);
        }
    }
    if (!LAST && lane == 0) nnzArr[brow] = lbase;
}

// ---------------------------------------------------------------------------
// Prep / misc kernels
// ---------------------------------------------------------------------------
__global__ void transpose_w_kernel(const float* __restrict__ Win,
                                   float* __restrict__ wt)
{
    __shared__ float tile[32][33];
    int n0 = blockIdx.x * 32;
    int m0 = blockIdx.y * 32;
    int tx = threadIdx.x, ty = threadIdx.y;
    for (int i = ty; i < 32; i += 8)
        tile[i][tx] = Win[(size_t)(m0 + i) * Ndim + n0 + tx];
    __syncthreads();
    for (int i = ty; i < 32; i += 8)
        wt[(size_t)(n0 + i) * Mdim + m0 + tx] = tile[tx][i];
}

__global__ void neg_copy_kernel(const float* __restrict__ src,
                                float* __restrict__ dst, size_t n)
{
    size_t i = ((size_t)blockIdx.x * blockDim.x + threadIdx.x) * 4;
    if (i < n) {
        float4 vq = *(const float4*)(src + i);
        vq.x = -vq.x; vq.y = -vq.y; vq.z = -vq.z; vq.w = -vq.w;
        *(float4*)(dst + i) = vq;
    }
}

__global__ void zero_kernel(float* __restrict__ p, size_t n)
{
    for (size_t i = (size_t)blockIdx.x * blockDim.x + threadIdx.x; i < n;
         i += (size_t)gridDim.x * blockDim.x)
        p[i] = 0.0f;
}

// ---------------------------------------------------------------------------
// Launch
// ---------------------------------------------------------------------------
extern "C" void kernel_launch(void* const* d_in, const int* in_sizes, int n_in,
                              void* d_out, int out_size)
{
    const float* y     = (const float*)d_in[0];
    const float* phi   = (const float*)d_in[1];
    const float* W     = (const float*)d_in[2];
    const float* gamma = (const float*)d_in[3];
    const float* theta = (const float*)d_in[4];
    float* out = (float*)d_out;

    float *xp, *rp, *cp, *wtp, *ptp;
    float2* spp;
    int* nnzp;
    cudaGetSymbolAddress((void**)&xp,   g_x);
    cudaGetSymbolAddress((void**)&rp,   g_r);
    cudaGetSymbolAddress((void**)&cp,   g_c);
    cudaGetSymbolAddress((void**)&wtp,  g_wt);
    cudaGetSymbolAddress((void**)&ptp,  g_phiT);
    cudaGetSymbolAddress((void**)&spp,  g_sp);
    cudaGetSymbolAddress((void**)&nnzp, g_nnz);

    cudaFuncSetAttribute(gemm_tc, cudaFuncAttributeMaxDynamicSharedMemorySize,
                         GEMM_SMEM);
    cudaFuncSetAttribute(sparse_gemm_kernel,
                         cudaFuncAttributeMaxDynamicSharedMemorySize, SPG_SMEM);

    // preprocessing: W^T, phi^T (both 256x1024 -> 1024x256)
    transpose_w_kernel<<<dim3(Ndim / 32, Mdim / 32), dim3(32, 8)>>>(W, wtp);
    transpose_w_kernel<<<dim3(Ndim / 32, Mdim / 32), dim3(32, 8)>>>(phi, ptp);
    zero_kernel<<<2048, 256>>>(xp, (size_t)Bdim * Ndim);

    for (int it = 0; it < Kiter; it++) {
        // r = x @ phi^T - y   (it 0: x = 0 -> r = -y; else sparse product)
        if (it == 0) {
            neg_copy_kernel<<<(Bdim * Mdim / 4 + 255) / 256, 256>>>(
                y, rp, (size_t)Bdim * Mdim);
        } else {
            sparse_gemm_kernel<<<dim3(Mdim / 32, Bdim / 128), 256, SPG_SMEM>>>(
                ptp, spp, nnzp, y, rp);
        }
        // c = r @ W   (dense tf32x3 tensor GEMM; B operand = W^T, k over M)
        gemm_tc<<<dim3(Ndim / 128, Bdim / 128), 256, GEMM_SMEM>>>(
            rp, wtp, cp, Mdim, Ndim);
        // x = soft_threshold(x - gamma*c, theta*g(|x|), 50) [+ list emit]
        if (it == Kiter - 1)
            update_kernel<1><<<Bdim / 8, 256>>>(xp, out, cp, spp, nnzp,
                                                gamma, theta, it);
        else
            update_kernel<0><<<Bdim / 8, 256>>>(xp, xp, cp, spp, nnzp,
                                                gamma, theta, it);
    }

    // zero the tail (the two (K,1) zero outputs appended after x)
    long long tail = (long long)out_size - (long long)Ndim * Bdim;
    if (tail > 0)
        zero_kernel<<<1, 256>>>(out + (size_t)Ndim * Bdim, (size_t)tail);
}

// round 9
// speedup vs baseline: 13.4355x; 13.4355x over previous
#include <cuda_runtime.h>
#include <cstdint>
#include <cstddef>

#define Mdim 256
#define Ndim 1024
#define Bdim 16384
#define Kiter 16
#define Pk 50u

// ---------------------------------------------------------------------------
// Scratch (allocation-free __device__ globals). Batch-major layout.
// Big tensors fp32; small constant matrices pre-split into tf32 hi/lo.
// ---------------------------------------------------------------------------
__device__ float g_x [(size_t)Bdim * Ndim];      // x (B,N)
__device__ float g_r [(size_t)Bdim * Mdim];      // r (B,M)
__device__ float g_c [(size_t)Bdim * Ndim];      // c (B,N)
__device__ float g_phihi[(size_t)Mdim * Ndim];   // phi (M,N), k=n contiguous
__device__ float g_philo[(size_t)Mdim * Ndim];
__device__ float g_wthi [(size_t)Ndim * Mdim];   // W^T (N,M), k=m contiguous
__device__ float g_wtlo [(size_t)Ndim * Mdim];

// ---------------------------------------------------------------------------
// PTX helpers (plain-sm_103-legal: cp.async sm_80+, mma.sync tf32 sm_80+)
// ---------------------------------------------------------------------------
__device__ __forceinline__ void cp_async16(uint32_t saddr, const void* gaddr) {
    asm volatile("cp.async.cg.shared.global [%0], [%1], 16;\n"
                 :: "r"(saddr), "l"(gaddr));
}
#define CP_COMMIT() asm volatile("cp.async.commit_group;\n" ::: "memory")
#define CP_WAIT0()  asm volatile("cp.async.wait_group 0;\n" ::: "memory")
#define CP_WAIT1()  asm volatile("cp.async.wait_group 1;\n" ::: "memory")

__device__ __forceinline__ void split_tf32(float v, uint32_t& hi, uint32_t& lo) {
    uint32_t h;
    asm("cvt.rna.tf32.f32 %0, %1;" : "=r"(h) : "f"(v));
    float hf = __uint_as_float(h);
    asm("cvt.rna.tf32.f32 %0, %1;" : "=r"(lo) : "f"(v - hf));
    hi = h;
}

__device__ __forceinline__ void split_tf32f(float v, float& hi, float& lo) {
    uint32_t h, l;
    split_tf32(v, h, l);
    hi = __uint_as_float(h);
    lo = __uint_as_float(l);
}

__device__ __forceinline__ void mma_tf32(float* d, const uint32_t* a,
                                         const uint32_t* b) {
    asm volatile(
        "mma.sync.aligned.m16n8k8.row.col.f32.tf32.tf32.f32 "
        "{%0,%1,%2,%3}, {%4,%5,%6,%7}, {%8,%9}, {%0,%1,%2,%3};"
        : "+f"(d[0]), "+f"(d[1]), "+f"(d[2]), "+f"(d[3])
        : "r"(a[0]), "r"(a[1]), "r"(a[2]), "r"(a[3]),
          "r"(b[0]), "r"(b[1]));
}

// ---------------------------------------------------------------------------
// TF32x3 GEMM: D(B x Nrows) = A(B,Kd) @ (Bhi+Blo)(Nrows,Kd)^T [- Sub if SUBY]
// A fp32, split to tf32 hi/lo in registers at fragment load (R4-proven).
// B pre-split in global (constant matrices; L2-resident).
// Tile 128(b) x 128(n) x 16(k), 256 threads (2x4 warps), warp tile 64x32.
// R4 sync protocol: load(t+1) -> wait -> sync -> compute -> sync.
// ---------------------------------------------------------------------------
#define KTILE 16
#define ROWPAD 20
#define OPF (128 * ROWPAD)                   // 2560 floats per operand tile
#define STAGE_FLOATS (3 * OPF)               // A, Bhi, Blo
#define STAGE_BYTES (STAGE_FLOATS * 4)       // 30720 B
#define GEMM_SMEM (2 * STAGE_BYTES)          // 61440 B

template<int SUBY>
__global__ void __launch_bounds__(256)
gemm_tc(const float* __restrict__ A,
        const float* __restrict__ Bhi, const float* __restrict__ Blo,
        float* __restrict__ D, const float* __restrict__ Sub,
        int Kd, int CStride)
{
    extern __shared__ float sm[];
    const int tid  = threadIdx.x;
    const int wid  = tid >> 5;
    const int lane = tid & 31;
    const int gid  = lane >> 2;
    const int tig  = lane & 3;
    const int wm   = wid >> 2;       // 0..1 -> 64-row strip (batch)
    const int wn   = wid & 3;        // 0..3 -> 32-col strip (n)
    const int b0   = blockIdx.y * 128;
    const int n0   = blockIdx.x * 128;
    const uint32_t smbase = (uint32_t)__cvta_generic_to_shared(sm);

    float acc[4][4][4];
#pragma unroll
    for (int i = 0; i < 4; i++)
#pragma unroll
        for (int j = 0; j < 4; j++)
#pragma unroll
            for (int q = 0; q < 4; q++) acc[i][j][q] = 0.0f;

    // Stage loader: 3 operands x 128 rows x 4 chunks(16B); 6 cp.async/thread.
    auto load_stage = [&](int t, int buf) {
        const int k0 = t * KTILE;
        const uint32_t sb = smbase + buf * STAGE_BYTES;
#pragma unroll
        for (int l = 0; l < 2; l++) {
            int idx = tid + l * 256;           // 0..511
            int row = idx >> 2;                // 0..127
            int ch  = idx & 3;                 // 0..3
            uint32_t so = (row * ROWPAD + ch * 4) * 4;
            cp_async16(sb + so, A + (size_t)(b0 + row) * Kd + k0 + ch * 4);
            cp_async16(sb + OPF * 4 + so,
                       Bhi + (size_t)(n0 + row) * Kd + k0 + ch * 4);
            cp_async16(sb + 2 * OPF * 4 + so,
                       Blo + (size_t)(n0 + row) * Kd + k0 + ch * 4);
        }
    };

    const int T = Kd / KTILE;
    load_stage(0, 0);
    CP_COMMIT();

    for (int t = 0; t < T; t++) {
        const int buf = t & 1;
        if (t + 1 < T) {
            load_stage(t + 1, buf ^ 1);
            CP_COMMIT();
            CP_WAIT1();
        } else {
            CP_WAIT0();
        }
        __syncthreads();

        const float* As = sm + buf * STAGE_FLOATS;
        const float* Bh = As + OPF;
        const float* Bl = Bh + OPF;

#pragma unroll
        for (int s = 0; s < 2; s++) {
            const int kb = s * 8;
            uint32_t bhi[4][2], blo[4][2];
#pragma unroll
            for (int nt = 0; nt < 4; nt++) {
                int n = wn * 32 + nt * 8 + gid;
                bhi[nt][0] = __float_as_uint(Bh[n * ROWPAD + kb + tig]);
                bhi[nt][1] = __float_as_uint(Bh[n * ROWPAD + kb + tig + 4]);
                blo[nt][0] = __float_as_uint(Bl[n * ROWPAD + kb + tig]);
                blo[nt][1] = __float_as_uint(Bl[n * ROWPAD + kb + tig + 4]);
            }
#pragma unroll
            for (int mt = 0; mt < 4; mt++) {
                int m = wm * 64 + mt * 16 + gid;
                uint32_t ahi[4], alo[4];
                split_tf32(As[m * ROWPAD + kb + tig], ahi[0], alo[0]);
                split_tf32(As[(m + 8) * ROWPAD + kb + tig], ahi[1], alo[1]);
                split_tf32(As[m * ROWPAD + kb + tig + 4], ahi[2], alo[2]);
                split_tf32(As[(m + 8) * ROWPAD + kb + tig + 4], ahi[3], alo[3]);
#pragma unroll
                for (int nt = 0; nt < 4; nt++) {
                    mma_tf32(acc[mt][nt], ahi, bhi[nt]);
                    mma_tf32(acc[mt][nt], ahi, blo[nt]);
                    mma_tf32(acc[mt][nt], alo, bhi[nt]);
                }
            }
        }
        __syncthreads();
    }

    // Epilogue. Fragment: c0:(r,2c) c1:(r,2c+1) c2:(r+8,2c) c3:(r+8,2c+1)
#pragma unroll
    for (int mt = 0; mt < 4; mt++) {
        int r0 = b0 + wm * 64 + mt * 16 + gid;
#pragma unroll
        for (int nt = 0; nt < 4; nt++) {
            int col = n0 + wn * 32 + nt * 8 + tig * 2;
            float2 v0 = make_float2(acc[mt][nt][0], acc[mt][nt][1]);
            float2 v1 = make_float2(acc[mt][nt][2], acc[mt][nt][3]);
            if (SUBY) {
                float2 y0 = *(const float2*)(Sub + (size_t)r0 * CStride + col);
                float2 y1 = *(const float2*)(Sub + (size_t)(r0 + 8) * CStride + col);
                v0.x -= y0.x; v0.y -= y0.y;
                v1.x -= y1.x; v1.y -= y1.y;
            }
            *(float2*)(D + (size_t)r0 * CStride + col) = v0;
            *(float2*)(D + (size_t)(r0 + 8) * CStride + col) = v1;
        }
    }
}

// ---------------------------------------------------------------------------
// Fused update on (B,N): one warp per batch row.
// v = x - gamma*c; thr = exact Pk-th largest |v| (4-pass radix select on fp32
// bits); xout = (|v|>thr) ? v : soft(v, theta*g(|x|)).
// ---------------------------------------------------------------------------
__global__ void __launch_bounds__(256)
update_kernel(const float* __restrict__ x, float* __restrict__ xout,
              const float* __restrict__ c,
              const float* __restrict__ gammaArr,
              const float* __restrict__ thetaArr, int it)
{
    __shared__ float    v[8][1024];
    __shared__ unsigned hist[8][256];

    const int tid  = threadIdx.x;
    const int w    = tid >> 5;
    const int lane = tid & 31;
    const size_t base = ((size_t)blockIdx.x * 8 + w) * Ndim;
    const float gamma = gammaArr[it];
    const float theta = thetaArr[it];

    float xabs[32];
#pragma unroll
    for (int i = 0; i < 8; i++) {
        int n = i * 128 + lane * 4;
        float4 xv = *(const float4*)(x + base + n);
        float4 cc = *(const float4*)(c + base + n);
        xabs[i * 4 + 0] = fabsf(xv.x);
        xabs[i * 4 + 1] = fabsf(xv.y);
        xabs[i * 4 + 2] = fabsf(xv.z);
        xabs[i * 4 + 3] = fabsf(xv.w);
        float4 vv;
        vv.x = xv.x - gamma * cc.x;
        vv.y = xv.y - gamma * cc.y;
        vv.z = xv.z - gamma * cc.z;
        vv.w = xv.w - gamma * cc.w;
        *(float4*)(&v[w][n]) = vv;
    }
    __syncwarp();

    unsigned prefix = 0u, mask = 0u, k = Pk;
    unsigned* h = hist[w];
#pragma unroll
    for (int pass = 0; pass < 4; pass++) {
        const int shift = 24 - 8 * pass;
#pragma unroll
        for (int i = lane; i < 256; i += 32) h[i] = 0u;
        __syncwarp();
        for (int n = lane; n < 1024; n += 32) {
            unsigned e = __float_as_uint(v[w][n]) & 0x7FFFFFFFu;
            if ((e & mask) == prefix)
                atomicAdd(&h[(e >> shift) & 0xFFu], 1u);
        }
        __syncwarp();
        unsigned loc[8];
        unsigned s = 0u;
#pragma unroll
        for (int r = 7; r >= 0; r--) { s += h[lane * 8 + r]; loc[r] = s; }
        unsigned inc = s;
#pragma unroll
        for (int off = 1; off < 32; off <<= 1) {
            unsigned t = __shfl_down_sync(0xffffffffu, inc, off);
            if (lane + off < 32) inc += t;
        }
        const unsigned above = inc - s;
        unsigned dfound = 0u, kfound = 0u;
        bool found = false;
#pragma unroll
        for (int r = 7; r >= 0; r--) {
            unsigned cge  = above + loc[r];
            unsigned cge1 = above + (r < 7 ? loc[r + 1] : 0u);
            if (cge >= k && cge1 < k) {
                dfound = (unsigned)(lane * 8 + r);
                kfound = k - cge1;
                found = true;
            }
        }
        unsigned bal = __ballot_sync(0xffffffffu, found);
        int src = __ffs(bal) - 1;
        dfound = __shfl_sync(0xffffffffu, dfound, src);
        kfound = __shfl_sync(0xffffffffu, kfound, src);
        k = kfound;
        prefix |= dfound << shift;
        mask   |= 0xFFu << shift;
        __syncwarp();
    }
    const float thrv = __uint_as_float(prefix);

#pragma unroll
    for (int i = 0; i < 8; i++) {
        int n = i * 128 + lane * 4;
        float4 vv = *(const float4*)(&v[w][n]);
        float4 o;
        float* vp = &vv.x;
        float* op = &o.x;
#pragma unroll
        for (int jc = 0; jc < 4; jc++) {
            float val = vp[jc];
            float av = fabsf(val);
            float th = theta * (1.0f / (xabs[i * 4 + jc] / 0.1f + 1.0f));
            float st = copysignf(fmaxf(av - th, 0.0f), val);
            op[jc] = (av > thrv) ? val : st;
        }
        *(float4*)(xout + base + n) = o;
    }
}

// ---------------------------------------------------------------------------
// Prep / misc kernels
// ---------------------------------------------------------------------------
__global__ void split_kernel(const float* __restrict__ in, float* __restrict__ hi,
                             float* __restrict__ lo, size_t n)
{
    for (size_t i = (size_t)blockIdx.x * blockDim.x + threadIdx.x; i < n;
         i += (size_t)gridDim.x * blockDim.x) {
        float h, l;
        split_tf32f(in[i], h, l);
        hi[i] = h;
        lo[i] = l;
    }
}

__global__ void transpose_split_kernel(const float* __restrict__ Win,
                                       float* __restrict__ wthi,
                                       float* __restrict__ wtlo)
{
    __shared__ float tile[32][33];
    int n0 = blockIdx.x * 32;
    int m0 = blockIdx.y * 32;
    int tx = threadIdx.x, ty = threadIdx.y;
    for (int i = ty; i < 32; i += 8)
        tile[i][tx] = Win[(size_t)(m0 + i) * Ndim + n0 + tx];
    __syncthreads();
    for (int i = ty; i < 32; i += 8) {
        float h, l;
        split_tf32f(tile[tx][i], h, l);
        size_t o = (size_t)(n0 + i) * Mdim + m0 + tx;
        wthi[o] = h;
        wtlo[o] = l;
    }
}

__global__ void neg_copy_kernel(const float* __restrict__ src,
                                float* __restrict__ dst, size_t n)
{
    size_t i = ((size_t)blockIdx.x * blockDim.x + threadIdx.x) * 4;
    if (i < n) {
        float4 vq = *(const float4*)(src + i);
        vq.x = -vq.x; vq.y = -vq.y; vq.z = -vq.z; vq.w = -vq.w;
        *(float4*)(dst + i) = vq;
    }
}

__global__ void zero_kernel(float* __restrict__ p, size_t n)
{
    for (size_t i = (size_t)blockIdx.x * blockDim.x + threadIdx.x; i < n;
         i += (size_t)gridDim.x * blockDim.x)
        p[i] = 0.0f;
}

// ---------------------------------------------------------------------------
// Launch
// ---------------------------------------------------------------------------
extern "C" void kernel_launch(void* const* d_in, const int* in_sizes, int n_in,
                              void* d_out, int out_size)
{
    const float* y     = (const float*)d_in[0];
    const float* phi   = (const float*)d_in[1];
    const float* W     = (const float*)d_in[2];
    const float* gamma = (const float*)d_in[3];
    const float* theta = (const float*)d_in[4];
    float* out = (float*)d_out;

    float *xp, *rp, *cp, *phihi, *philo, *wthi, *wtlo;
    cudaGetSymbolAddress((void**)&xp,    g_x);
    cudaGetSymbolAddress((void**)&rp,    g_r);
    cudaGetSymbolAddress((void**)&cp,    g_c);
    cudaGetSymbolAddress((void**)&phihi, g_phihi);
    cudaGetSymbolAddress((void**)&philo, g_philo);
    cudaGetSymbolAddress((void**)&wthi,  g_wthi);
    cudaGetSymbolAddress((void**)&wtlo,  g_wtlo);

    cudaFuncSetAttribute(gemm_tc<1>, cudaFuncAttributeMaxDynamicSharedMemorySize,
                         GEMM_SMEM);
    cudaFuncSetAttribute(gemm_tc<0>, cudaFuncAttributeMaxDynamicSharedMemorySize,
                         GEMM_SMEM);

    split_kernel<<<512, 256>>>(phi, phihi, philo, (size_t)Mdim * Ndim);
    transpose_split_kernel<<<dim3(Ndim / 32, Mdim / 32), dim3(32, 8)>>>(W, wthi, wtlo);
    zero_kernel<<<2048, 256>>>(xp, (size_t)Bdim * Ndim);

    for (int it = 0; it < Kiter; it++) {
        // r = x @ phi^T - y  (it 0: x = 0 -> r = -y)
        if (it == 0) {
            neg_copy_kernel<<<(Bdim * Mdim / 4 + 255) / 256, 256>>>(
                y, rp, (size_t)Bdim * Mdim);
        } else {
            gemm_tc<1><<<dim3(Mdim / 128, Bdim / 128), 256, GEMM_SMEM>>>(
                xp, phihi, philo, rp, y, Ndim, Mdim);
        }
        // c = r @ W  (B operand = W^T pre-split, k-major over M)
        gemm_tc<0><<<dim3(Ndim / 128, Bdim / 128), 256, GEMM_SMEM>>>(
            rp, wthi, wtlo, cp, nullptr, Mdim, Ndim);
        // x = soft_threshold(x - gamma*c, theta*g(|x|), 50)
        float* xout = (it == Kiter - 1) ? out : xp;
        update_kernel<<<Bdim / 8, 256>>>(xp, xout, cp, gamma, theta, it);
    }

    // zero the tail (the two (K,1) zero outputs appended after x)
    long long tail = (long long)out_size - (long long)Ndim * Bdim;
    if (tail > 0)
        zero_kernel<<<1, 256>>>(out + (size_t)Ndim * Bdim, (size_t)tail);
}

// round 10
// speedup vs baseline: 13.8389x; 1.0300x over previous
#include <cuda_runtime.h>
#include <cstdint>
#include <cstddef>

#define Mdim 256
#define Ndim 1024
#define Bdim 16384
#define Kiter 16
#define Pk 50u

// ---------------------------------------------------------------------------
// Scratch (allocation-free __device__ globals). Batch-major layout.
// Big tensors fp32; small constant matrices pre-split into tf32 hi/lo.
// ---------------------------------------------------------------------------
__device__ float g_x [(size_t)Bdim * Ndim];      // x (B,N)
__device__ float g_r [(size_t)Bdim * Mdim];      // r (B,M)
__device__ float g_c [(size_t)Bdim * Ndim];      // c (B,N)
__device__ float g_phihi[(size_t)Mdim * Ndim];   // phi (M,N), k=n contiguous
__device__ float g_philo[(size_t)Mdim * Ndim];
__device__ float g_wthi [(size_t)Ndim * Mdim];   // W^T (N,M), k=m contiguous
__device__ float g_wtlo [(size_t)Ndim * Mdim];

// ---------------------------------------------------------------------------
// PTX helpers (plain-sm_103-legal: cp.async sm_80+, mma.sync tf32 sm_80+)
// ---------------------------------------------------------------------------
__device__ __forceinline__ void cp_async16(uint32_t saddr, const void* gaddr) {
    asm volatile("cp.async.cg.shared.global [%0], [%1], 16;\n"
                 :: "r"(saddr), "l"(gaddr));
}
#define CP_COMMIT() asm volatile("cp.async.commit_group;\n" ::: "memory")
#define CP_WAIT0()  asm volatile("cp.async.wait_group 0;\n" ::: "memory")
#define CP_WAIT1()  asm volatile("cp.async.wait_group 1;\n" ::: "memory")

__device__ __forceinline__ void split_tf32(float v, uint32_t& hi, uint32_t& lo) {
    uint32_t h;
    asm("cvt.rna.tf32.f32 %0, %1;" : "=r"(h) : "f"(v));
    float hf = __uint_as_float(h);
    asm("cvt.rna.tf32.f32 %0, %1;" : "=r"(lo) : "f"(v - hf));
    hi = h;
}

__device__ __forceinline__ void split_tf32f(float v, float& hi, float& lo) {
    uint32_t h, l;
    split_tf32(v, h, l);
    hi = __uint_as_float(h);
    lo = __uint_as_float(l);
}

__device__ __forceinline__ void mma_tf32(float* d, const uint32_t* a,
                                         const uint32_t* b) {
    asm volatile(
        "mma.sync.aligned.m16n8k8.row.col.f32.tf32.tf32.f32 "
        "{%0,%1,%2,%3}, {%4,%5,%6,%7}, {%8,%9}, {%0,%1,%2,%3};"
        : "+f"(d[0]), "+f"(d[1]), "+f"(d[2]), "+f"(d[3])
        : "r"(a[0]), "r"(a[1]), "r"(a[2]), "r"(a[3]),
          "r"(b[0]), "r"(b[1]));
}

// ---------------------------------------------------------------------------
// TF32x3 GEMM: D(B x Nrows) = A(B,Kd) @ (Bhi+Blo)(Nrows,Kd)^T [- Sub if SUBY]
// A fp32, split to tf32 hi/lo in registers at fragment load.
// B pre-split in global (constant matrices; L2-resident).
// Tile 128(b) x 128(n) x 16(k), 256 threads (2x4 warps), warp tile 64x32.
// MMA issue order is TERM-MAJOR so consecutive MMAs hit different
// accumulators (dependency distance 4 instead of 1).
// ---------------------------------------------------------------------------
#define KTILE 16
#define ROWPAD 20
#define OPF (128 * ROWPAD)                   // 2560 floats per operand tile
#define STAGE_FLOATS (3 * OPF)               // A, Bhi, Blo
#define STAGE_BYTES (STAGE_FLOATS * 4)       // 30720 B
#define GEMM_SMEM (2 * STAGE_BYTES)          // 61440 B

template<int SUBY>
__global__ void __launch_bounds__(256)
gemm_tc(const float* __restrict__ A,
        const float* __restrict__ Bhi, const float* __restrict__ Blo,
        float* __restrict__ D, const float* __restrict__ Sub,
        int Kd, int CStride)
{
    extern __shared__ float sm[];
    const int tid  = threadIdx.x;
    const int wid  = tid >> 5;
    const int lane = tid & 31;
    const int gid  = lane >> 2;
    const int tig  = lane & 3;
    const int wm   = wid >> 2;       // 0..1 -> 64-row strip (batch)
    const int wn   = wid & 3;        // 0..3 -> 32-col strip (n)
    const int b0   = blockIdx.y * 128;
    const int n0   = blockIdx.x * 128;
    const uint32_t smbase = (uint32_t)__cvta_generic_to_shared(sm);

    float acc[4][4][4];
#pragma unroll
    for (int i = 0; i < 4; i++)
#pragma unroll
        for (int j = 0; j < 4; j++)
#pragma unroll
            for (int q = 0; q < 4; q++) acc[i][j][q] = 0.0f;

    // Stage loader: 3 operands x 128 rows x 4 chunks(16B); 6 cp.async/thread.
    auto load_stage = [&](int t, int buf) {
        const int k0 = t * KTILE;
        const uint32_t sb = smbase + buf * STAGE_BYTES;
#pragma unroll
        for (int l = 0; l < 2; l++) {
            int idx = tid + l * 256;           // 0..511
            int row = idx >> 2;                // 0..127
            int ch  = idx & 3;                 // 0..3
            uint32_t so = (row * ROWPAD + ch * 4) * 4;
            cp_async16(sb + so, A + (size_t)(b0 + row) * Kd + k0 + ch * 4);
            cp_async16(sb + OPF * 4 + so,
                       Bhi + (size_t)(n0 + row) * Kd + k0 + ch * 4);
            cp_async16(sb + 2 * OPF * 4 + so,
                       Blo + (size_t)(n0 + row) * Kd + k0 + ch * 4);
        }
    };

    const int T = Kd / KTILE;
    load_stage(0, 0);
    CP_COMMIT();

    for (int t = 0; t < T; t++) {
        const int buf = t & 1;
        if (t + 1 < T) {
            load_stage(t + 1, buf ^ 1);
            CP_COMMIT();
            CP_WAIT1();
        } else {
            CP_WAIT0();
        }
        __syncthreads();

        const float* As = sm + buf * STAGE_FLOATS;
        const float* Bh = As + OPF;
        const float* Bl = Bh + OPF;

#pragma unroll
        for (int s = 0; s < 2; s++) {
            const int kb = s * 8;
            uint32_t bhi[4][2], blo[4][2];
#pragma unroll
            for (int nt = 0; nt < 4; nt++) {
                int n = wn * 32 + nt * 8 + gid;
                bhi[nt][0] = __float_as_uint(Bh[n * ROWPAD + kb + tig]);
                bhi[nt][1] = __float_as_uint(Bh[n * ROWPAD + kb + tig + 4]);
                blo[nt][0] = __float_as_uint(Bl[n * ROWPAD + kb + tig]);
                blo[nt][1] = __float_as_uint(Bl[n * ROWPAD + kb + tig + 4]);
            }
#pragma unroll
            for (int mt = 0; mt < 4; mt++) {
                int m = wm * 64 + mt * 16 + gid;
                uint32_t ahi[4], alo[4];
                split_tf32(As[m * ROWPAD + kb + tig], ahi[0], alo[0]);
                split_tf32(As[(m + 8) * ROWPAD + kb + tig], ahi[1], alo[1]);
                split_tf32(As[m * ROWPAD + kb + tig + 4], ahi[2], alo[2]);
                split_tf32(As[(m + 8) * ROWPAD + kb + tig + 4], ahi[3], alo[3]);
                // term-major: consecutive MMAs touch different accumulators
#pragma unroll
                for (int nt = 0; nt < 4; nt++)
                    mma_tf32(acc[mt][nt], ahi, bhi[nt]);
#pragma unroll
                for (int nt = 0; nt < 4; nt++)
                    mma_tf32(acc[mt][nt], ahi, blo[nt]);
#pragma unroll
                for (int nt = 0; nt < 4; nt++)
                    mma_tf32(acc[mt][nt], alo, bhi[nt]);
            }
        }
        __syncthreads();
    }

    // Epilogue. Fragment: c0:(r,2c) c1:(r,2c+1) c2:(r+8,2c) c3:(r+8,2c+1)
#pragma unroll
    for (int mt = 0; mt < 4; mt++) {
        int r0 = b0 + wm * 64 + mt * 16 + gid;
#pragma unroll
        for (int nt = 0; nt < 4; nt++) {
            int col = n0 + wn * 32 + nt * 8 + tig * 2;
            float2 v0 = make_float2(acc[mt][nt][0], acc[mt][nt][1]);
            float2 v1 = make_float2(acc[mt][nt][2], acc[mt][nt][3]);
            if (SUBY) {
                float2 y0 = *(const float2*)(Sub + (size_t)r0 * CStride + col);
                float2 y1 = *(const float2*)(Sub + (size_t)(r0 + 8) * CStride + col);
                v0.x -= y0.x; v0.y -= y0.y;
                v1.x -= y1.x; v1.y -= y1.y;
            }
            *(float2*)(D + (size_t)r0 * CStride + col) = v0;
            *(float2*)(D + (size_t)(r0 + 8) * CStride + col) = v1;
        }
    }
}

// ---------------------------------------------------------------------------
// Fused update on (B,N): one warp per batch row.
// v = x - gamma*c; thr = exact Pk-th largest |v| (4-pass radix select on fp32
// bits); xout = (|v|>thr) ? v : soft(v, theta*g(|x|)).
// ---------------------------------------------------------------------------
__global__ void __launch_bounds__(256)
update_kernel(const float* __restrict__ x, float* __restrict__ xout,
              const float* __restrict__ c,
              const float* __restrict__ gammaArr,
              const float* __restrict__ thetaArr, int it)
{
    __shared__ float    v[8][1024];
    __shared__ unsigned hist[8][256];

    const int tid  = threadIdx.x;
    const int w    = tid >> 5;
    const int lane = tid & 31;
    const size_t base = ((size_t)blockIdx.x * 8 + w) * Ndim;
    const float gamma = gammaArr[it];
    const float theta = thetaArr[it];

    float xabs[32];
#pragma unroll
    for (int i = 0; i < 8; i++) {
        int n = i * 128 + lane * 4;
        float4 xv = *(const float4*)(x + base + n);
        float4 cc = *(const float4*)(c + base + n);
        xabs[i * 4 + 0] = fabsf(xv.x);
        xabs[i * 4 + 1] = fabsf(xv.y);
        xabs[i * 4 + 2] = fabsf(xv.z);
        xabs[i * 4 + 3] = fabsf(xv.w);
        float4 vv;
        vv.x = xv.x - gamma * cc.x;
        vv.y = xv.y - gamma * cc.y;
        vv.z = xv.z - gamma * cc.z;
        vv.w = xv.w - gamma * cc.w;
        *(float4*)(&v[w][n]) = vv;
    }
    __syncwarp();

    unsigned prefix = 0u, mask = 0u, k = Pk;
    unsigned* h = hist[w];
#pragma unroll
    for (int pass = 0; pass < 4; pass++) {
        const int shift = 24 - 8 * pass;
#pragma unroll
        for (int i = lane; i < 256; i += 32) h[i] = 0u;
        __syncwarp();
        for (int n = lane; n < 1024; n += 32) {
            unsigned e = __float_as_uint(v[w][n]) & 0x7FFFFFFFu;
            if ((e & mask) == prefix)
                atomicAdd(&h[(e >> shift) & 0xFFu], 1u);
        }
        __syncwarp();
        unsigned loc[8];
        unsigned s = 0u;
#pragma unroll
        for (int r = 7; r >= 0; r--) { s += h[lane * 8 + r]; loc[r] = s; }
        unsigned inc = s;
#pragma unroll
        for (int off = 1; off < 32; off <<= 1) {
            unsigned t = __shfl_down_sync(0xffffffffu, inc, off);
            if (lane + off < 32) inc += t;
        }
        const unsigned above = inc - s;
        unsigned dfound = 0u, kfound = 0u;
        bool found = false;
#pragma unroll
        for (int r = 7; r >= 0; r--) {
            unsigned cge  = above + loc[r];
            unsigned cge1 = above + (r < 7 ? loc[r + 1] : 0u);
            if (cge >= k && cge1 < k) {
                dfound = (unsigned)(lane * 8 + r);
                kfound = k - cge1;
                found = true;
            }
        }
        unsigned bal = __ballot_sync(0xffffffffu, found);
        int src = __ffs(bal) - 1;
        dfound = __shfl_sync(0xffffffffu, dfound, src);
        kfound = __shfl_sync(0xffffffffu, kfound, src);
        k = kfound;
        prefix |= dfound << shift;
        mask   |= 0xFFu << shift;
        __syncwarp();
    }
    const float thrv = __uint_as_float(prefix);

#pragma unroll
    for (int i = 0; i < 8; i++) {
        int n = i * 128 + lane * 4;
        float4 vv = *(const float4*)(&v[w][n]);
        float4 o;
        float* vp = &vv.x;
        float* op = &o.x;
#pragma unroll
        for (int jc = 0; jc < 4; jc++) {
            float val = vp[jc];
            float av = fabsf(val);
            float th = theta * (1.0f / (xabs[i * 4 + jc] / 0.1f + 1.0f));
            float st = copysignf(fmaxf(av - th, 0.0f), val);
            op[jc] = (av > thrv) ? val : st;
        }
        *(float4*)(xout + base + n) = o;
    }
}

// ---------------------------------------------------------------------------
// Prep / misc kernels
// ---------------------------------------------------------------------------
__global__ void split_kernel(const float* __restrict__ in, float* __restrict__ hi,
                             float* __restrict__ lo, size_t n)
{
    for (size_t i = (size_t)blockIdx.x * blockDim.x + threadIdx.x; i < n;
         i += (size_t)gridDim.x * blockDim.x) {
        float h, l;
        split_tf32f(in[i], h, l);
        hi[i] = h;
        lo[i] = l;
    }
}

__global__ void transpose_split_kernel(const float* __restrict__ Win,
                                       float* __restrict__ wthi,
                                       float* __restrict__ wtlo)
{
    __shared__ float tile[32][33];
    int n0 = blockIdx.x * 32;
    int m0 = blockIdx.y * 32;
    int tx = threadIdx.x, ty = threadIdx.y;
    for (int i = ty; i < 32; i += 8)
        tile[i][tx] = Win[(size_t)(m0 + i) * Ndim + n0 + tx];
    __syncthreads();
    for (int i = ty; i < 32; i += 8) {
        float h, l;
        split_tf32f(tile[tx][i], h, l);
        size_t o = (size_t)(n0 + i) * Mdim + m0 + tx;
        wthi[o] = h;
        wtlo[o] = l;
    }
}

__global__ void neg_copy_kernel(const float* __restrict__ src,
                                float* __restrict__ dst, size_t n)
{
    size_t i = ((size_t)blockIdx.x * blockDim.x + threadIdx.x) * 4;
    if (i < n) {
        float4 vq = *(const float4*)(src + i);
        vq.x = -vq.x; vq.y = -vq.y; vq.z = -vq.z; vq.w = -vq.w;
        *(float4*)(dst + i) = vq;
    }
}

__global__ void zero_kernel(float* __restrict__ p, size_t n)
{
    for (size_t i = (size_t)blockIdx.x * blockDim.x + threadIdx.x; i < n;
         i += (size_t)gridDim.x * blockDim.x)
        p[i] = 0.0f;
}

// ---------------------------------------------------------------------------
// Launch
// ---------------------------------------------------------------------------
extern "C" void kernel_launch(void* const* d_in, const int* in_sizes, int n_in,
                              void* d_out, int out_size)
{
    const float* y     = (const float*)d_in[0];
    const float* phi   = (const float*)d_in[1];
    const float* W     = (const float*)d_in[2];
    const float* gamma = (const float*)d_in[3];
    const float* theta = (const float*)d_in[4];
    float* out = (float*)d_out;

    float *xp, *rp, *cp, *phihi, *philo, *wthi, *wtlo;
    cudaGetSymbolAddress((void**)&xp,    g_x);
    cudaGetSymbolAddress((void**)&rp,    g_r);
    cudaGetSymbolAddress((void**)&cp,    g_c);
    cudaGetSymbolAddress((void**)&phihi, g_phihi);
    cudaGetSymbolAddress((void**)&philo, g_philo);
    cudaGetSymbolAddress((void**)&wthi,  g_wthi);
    cudaGetSymbolAddress((void**)&wtlo,  g_wtlo);

    cudaFuncSetAttribute(gemm_tc<1>, cudaFuncAttributeMaxDynamicSharedMemorySize,
                         GEMM_SMEM);
    cudaFuncSetAttribute(gemm_tc<0>, cudaFuncAttributeMaxDynamicSharedMemorySize,
                         GEMM_SMEM);

    split_kernel<<<512, 256>>>(phi, phihi, philo, (size_t)Mdim * Ndim);
    transpose_split_kernel<<<dim3(Ndim / 32, Mdim / 32), dim3(32, 8)>>>(W, wthi, wtlo);
    zero_kernel<<<2048, 256>>>(xp, (size_t)Bdim * Ndim);

    for (int it = 0; it < Kiter; it++) {
        // r = x @ phi^T - y  (it 0: x = 0 -> r = -y)
        if (it == 0) {
            neg_copy_kernel<<<(Bdim * Mdim / 4 + 255) / 256, 256>>>(
                y, rp, (size_t)Bdim * Mdim);
        } else {
            gemm_tc<1><<<dim3(Mdim / 128, Bdim / 128), 256, GEMM_SMEM>>>(
                xp, phihi, philo, rp, y, Ndim, Mdim);
        }
        // c = r @ W  (B operand = W^T pre-split, k-major over M)
        gemm_tc<0><<<dim3(Ndim / 128, Bdim / 128), 256, GEMM_SMEM>>>(
            rp, wthi, wtlo, cp, nullptr, Mdim, Ndim);
        // x = soft_threshold(x - gamma*c, theta*g(|x|), 50)
        float* xout = (it == Kiter - 1) ? out : xp;
        update_kernel<<<Bdim / 8, 256>>>(xp, xout, cp, gamma, theta, it);
    }

    // zero the tail (the two (K,1) zero outputs appended after x)
    long long tail = (long long)out_size - (long long)Ndim * Bdim;
    if (tail > 0)
        zero_kernel<<<1, 256>>>(out + (size_t)Ndim * Bdim, (size_t)tail);
}